// round 15
// baseline (speedup 1.0000x reference)
#include <cuda_runtime.h>
#include <cuda_bf16.h>
#include <cuda_fp16.h>
#include <cstdint>
#include <cstddef>

// Problem dims
#define Bv  4
#define Qv  1024
#define Kv  1024
#define Dv  256
#define Hv  64
#define DVv 256

// Scratch (allocation-free rule: __device__ globals)
__device__ __align__(16) __half g_qp[Bv * Qv * Hv];                 // 512 KB
__device__ __align__(16) __half g_kp[Bv * Kv * Hv];                 // 512 KB
__device__ __align__(16) __half g_a[(size_t)Bv * Qv * Kv];          // 8 MB  (fp16 attn)
__device__ __align__(16) __half g_v[Bv * Kv * DVv];                 // 2 MB  (fp16 values)

__device__ __forceinline__ uint32_t tanh2(uint32_t x) {
    uint32_t y;
    asm("tanh.approx.f16x2 %0, %1;" : "=r"(y) : "r"(x));
    return y;
}

__device__ __forceinline__ uint32_t s2u(const void* p) {
    uint32_t a;
    asm("{ .reg .u64 t; cvta.to.shared.u64 t, %1; cvt.u32.u64 %0, t; }" : "=r"(a) : "l"(p));
    return a;
}

__device__ __forceinline__ void cp16(uint32_t dst, const void* src) {
    asm volatile("cp.async.cg.shared.global [%0], [%1], 16;" :: "r"(dst), "l"(src));
}
__device__ __forceinline__ void cp_commit() { asm volatile("cp.async.commit_group;"); }
template <int N> __device__ __forceinline__ void cp_wait() {
    asm volatile("cp.async.wait_group %0;" :: "n"(N));
}

__device__ __forceinline__ void ldsm4(uint32_t* r, uint32_t addr) {
    asm volatile("ldmatrix.sync.aligned.m8n8.x4.shared.b16 {%0,%1,%2,%3}, [%4];"
                 : "=r"(r[0]), "=r"(r[1]), "=r"(r[2]), "=r"(r[3]) : "r"(addr));
}
__device__ __forceinline__ void ldsm4t(uint32_t* r, uint32_t addr) {
    asm volatile("ldmatrix.sync.aligned.m8n8.x4.trans.shared.b16 {%0,%1,%2,%3}, [%4];"
                 : "=r"(r[0]), "=r"(r[1]), "=r"(r[2]), "=r"(r[3]) : "r"(addr));
}
__device__ __forceinline__ void mma_bf16(float* d, const uint32_t* a, const uint32_t* b) {
    asm volatile(
        "mma.sync.aligned.m16n8k16.row.col.f32.bf16.bf16.f32 "
        "{%0,%1,%2,%3},{%4,%5,%6,%7},{%8,%9},{%0,%1,%2,%3};"
        : "+f"(d[0]), "+f"(d[1]), "+f"(d[2]), "+f"(d[3])
        : "r"(a[0]), "r"(a[1]), "r"(a[2]), "r"(a[3]), "r"(b[0]), "r"(b[1]));
}
__device__ __forceinline__ void mma_f16(float* d, const uint32_t* a, const uint32_t* b) {
    asm volatile(
        "mma.sync.aligned.m16n8k16.row.col.f32.f16.f16.f32 "
        "{%0,%1,%2,%3},{%4,%5,%6,%7},{%8,%9},{%0,%1,%2,%3};"
        : "+f"(d[0]), "+f"(d[1]), "+f"(d[2]), "+f"(d[3])
        : "r"(a[0]), "r"(a[1]), "r"(a[2]), "r"(a[3]), "r"(b[0]), "r"(b[1]));
}

__device__ __forceinline__ void bfsplit2(float x, float y, uint32_t& hi, uint32_t& lo) {
    __nv_bfloat16 hx = __float2bfloat16(x), hy = __float2bfloat16(y);
    __nv_bfloat16 lx = __float2bfloat16(x - __bfloat162float(hx));
    __nv_bfloat16 ly = __float2bfloat16(y - __bfloat162float(hy));
    hi = (uint32_t)*(uint16_t*)&hx | ((uint32_t)*(uint16_t*)&hy << 16);
    lo = (uint32_t)*(uint16_t*)&lx | ((uint32_t)*(uint16_t*)&ly << 16);
}

// ---------------------------------------------------------------------------
// Fused: projections via bf16x3 HMMA + values fp16 convert.
// grid (1, 256), 256 threads: y<64 Q tiles (64 rows), y<128 K tiles, else vconv.
// 8 warps, warp tile 16(M) x 32(N).
// ---------------------------------------------------------------------------
#define PW_STRIDE 72
#define PA_STRIDE 40
#define PJ_WPLANE (256 * PW_STRIDE * 2)     // 36864 B
#define PJ_W_BYTES (2 * PJ_WPLANE)          // 73728
#define PJ_APLANE (64 * PA_STRIDE * 2)      // 5120 B
#define PJ_ABUF   (2 * PJ_APLANE)           // 10240 per stage
#define PJ_SMEM_TOTAL (PJ_W_BYTES + 2 * PJ_ABUF)   // 94208

__global__ __launch_bounds__(256)
void proj_vsplit_kernel(const float* __restrict__ Qg, const float* __restrict__ Kg,
                        const float* __restrict__ Wq, const float* __restrict__ Wk,
                        const float* __restrict__ Vg)
{
    if (blockIdx.y >= 128) {
        const int blk = blockIdx.y - 128;          // 0..127
#pragma unroll
        for (int it = 0; it < 8; it++) {
            size_t idx4 = (size_t)blk * 256 + threadIdx.x + (size_t)it * 32768;
            size_t i = idx4 * 4;
            float4 v = *(const float4*)(Vg + i);
            __half2 p01 = __floats2half2_rn(v.x, v.y);
            __half2 p23 = __floats2half2_rn(v.z, v.w);
            *(uint2*)(g_v + i) = make_uint2(*(uint32_t*)&p01, *(uint32_t*)&p23);
        }
        return;
    }

    extern __shared__ char psm[];
    char* wh = psm;
    char* wl = psm + PJ_WPLANE;
    char* ab = psm + PJ_W_BYTES;
    const uint32_t sWH = s2u(wh);
    const uint32_t sWL = s2u(wl);
    const uint32_t sAB = s2u(ab);

    const bool isQ = blockIdx.y < 64;
    const int tile = blockIdx.y & 63;
    const float* A = (isQ ? Qg : Kg) + (size_t)tile * 64 * 256;
    const float* W = isQ ? Wq : Wk;
    __half*      C = (isQ ? g_qp : g_kp) + (size_t)tile * 64 * 64;

    const int t = threadIdx.x;
    const int wid = t >> 5, lane = t & 31;
    const int wm = wid & 3;        // 4 m-slices of 16 rows
    const int wn = wid >> 2;       // 2 n-slices of 32 cols

    // A register staging: thread owns 8 consecutive k of one row per stage
    const int ar = t >> 2;                 // 0..63
    const int akc = (t & 3) * 8;           // 0,8,16,24
    float4 rA[2], rB[2];

    auto ldgA = [&](int s, float4* rg) {
        const float* src = A + (size_t)ar * 256 + s * 32 + akc;
        rg[0] = *(const float4*)(src);
        rg[1] = *(const float4*)(src + 4);
    };
    auto stsA = [&](const float4* rg, int buf) {
        char* hb = ab + buf * PJ_ABUF + (ar * PA_STRIDE + akc) * 2;
        char* lb = hb + PJ_APLANE;
#pragma unroll
        for (int j = 0; j < 2; j++) {
            uint32_t h01, l01, h23, l23;
            bfsplit2(rg[j].x, rg[j].y, h01, l01);
            bfsplit2(rg[j].z, rg[j].w, h23, l23);
            *(uint2*)(hb + j * 8) = make_uint2(h01, h23);
            *(uint2*)(lb + j * 8) = make_uint2(l01, l23);
        }
    };

    ldgA(0, rA);

    // one-time W f32 -> bf16 hi/lo smem (4096 float4 over 256 threads)
#pragma unroll
    for (int i = 0; i < 16; i++) {
        int idx = t + i * 256;
        int row = idx >> 4;
        int c4 = (idx & 15) * 4;
        float4 v = *(const float4*)(W + (size_t)row * 64 + c4);
        uint32_t h01, l01, h23, l23;
        bfsplit2(v.x, v.y, h01, l01);
        bfsplit2(v.z, v.w, h23, l23);
        *(uint2*)(wh + (row * PW_STRIDE + c4) * 2) = make_uint2(h01, h23);
        *(uint2*)(wl + (row * PW_STRIDE + c4) * 2) = make_uint2(l01, l23);
    }

    stsA(rA, 0);
    __syncthreads();

    const int sub = lane >> 3, r8 = lane & 7;
    const uint32_t a_off = (uint32_t)(((sub & 1) * 8 + r8) * (PA_STRIDE * 2) + (sub >> 1) * 16);
    const uint32_t w_off = (uint32_t)(((sub & 1) * 8 + r8) * (PW_STRIDE * 2) + (sub >> 1) * 16);

    float acc[4][4] = {};

    for (int s = 0; s < 8; s++) {
        const int buf = s & 1;
        if (s < 7) ldgA(s + 1, rB);

#pragma unroll
        for (int kk2 = 0; kk2 < 2; kk2++) {
            const int kk = kk2 * 16;
            const int kg = s * 32 + kk;      // global k for persistent W
            uint32_t Ah4[4], Al4[4];
            {
                uint32_t base = sAB + (uint32_t)(buf * PJ_ABUF)
                              + (uint32_t)((wm * 16 * PA_STRIDE + kk) * 2) + a_off;
                ldsm4(Ah4, base);
                ldsm4(Al4, base + PJ_APLANE);
            }
            uint32_t Wh4[4][2], Wl4[4][2];
#pragma unroll
            for (int p = 0; p < 2; p++) {
                uint32_t rr[4];
                uint32_t co = (uint32_t)(kg * PW_STRIDE * 2) + (uint32_t)(wn * 64 + p * 32) + w_off;
                ldsm4t(rr, sWH + co);
                Wh4[2 * p][0] = rr[0]; Wh4[2 * p][1] = rr[1];
                Wh4[2 * p + 1][0] = rr[2]; Wh4[2 * p + 1][1] = rr[3];
                ldsm4t(rr, sWL + co);
                Wl4[2 * p][0] = rr[0]; Wl4[2 * p][1] = rr[1];
                Wl4[2 * p + 1][0] = rr[2]; Wl4[2 * p + 1][1] = rr[3];
            }
#pragma unroll
            for (int nt = 0; nt < 4; nt++) {
                mma_bf16(acc[nt], Ah4, Wh4[nt]);
                mma_bf16(acc[nt], Ah4, Wl4[nt]);
                mma_bf16(acc[nt], Al4, Wh4[nt]);
            }
        }

        if (s < 7) stsA(rB, buf ^ 1);
        __syncthreads();
    }

    const int g = lane >> 2, tq = lane & 3;
#pragma unroll
    for (int nt = 0; nt < 4; nt++) {
        int col = wn * 32 + nt * 8 + tq * 2;
        int row0 = wm * 16 + g;
        __half2 p0 = __floats2half2_rn(acc[nt][0], acc[nt][1]);
        __half2 p1 = __floats2half2_rn(acc[nt][2], acc[nt][3]);
        *(__half2*)(C + (size_t)row0 * 64 + col)       = p0;
        *(__half2*)(C + (size_t)(row0 + 8) * 64 + col) = p1;
    }
}

// ---------------------------------------------------------------------------
// Fused scores + softmax: QT=16, 256 threads, 83 KB smem -> 2 CTAs/SM,
// grid (64, 4) = 256 CTAs. Each thread: 2 q-rows x 2 k-slots.
// ---------------------------------------------------------------------------
#define QT 16
#define SC_BYTES   (QT * 1024 * 4)          // 65536
#define QP_OFF     SC_BYTES
#define QP_BYTES   (QT * 33 * 8)            // 4224
#define KP_OFF     (QP_OFF + QP_BYTES)
#define KP_BYTES   (2 * 64 * 33 * 4)        // 16896
#define WV_OFF     (KP_OFF + KP_BYTES)
#define SMEM_SC_TOTAL (WV_OFF + 128)        // 86784

__global__ __launch_bounds__(256)
void scores_softmax_kernel(const float* __restrict__ wv_g)
{
    extern __shared__ char sm[];
    float   (*s_sc)[1024]   = (float(*)[1024])sm;
    __half2 (*s_qp)[33]     = (__half2(*)[33])(sm + QP_OFF);
    __half2 (*s_kp)[64][33] = (__half2(*)[64][33])(sm + KP_OFF);
    __half2* s_wv           = (__half2*)(sm + WV_OFF);

    const int t  = threadIdx.x;
    const int b  = blockIdx.y;
    const int q0 = blockIdx.x * QT;

    const __half2* qp = (const __half2*)(g_qp + ((size_t)b * Qv + q0) * Hv);
    const __half2* kp = (const __half2*)(g_kp + (size_t)b * Kv * Hv);

    // qp: 16x32 half2 = 512 -> 2 per thread
#pragma unroll
    for (int j = 0; j < 2; j++) {
        int i = t + j * 256;
        s_qp[i >> 5][i & 31] = qp[i];
    }
    if (t < 32) s_wv[t] = __floats2half2_rn(wv_g[2 * t], wv_g[2 * t + 1]);

    // kp chunk 0: 2048 half2 -> 8 per thread
#pragma unroll
    for (int j = 0; j < 8; j++) {
        int i = t + j * 256;
        s_kp[0][i >> 5][i & 31] = kp[i];
    }
    __syncthreads();

    const int tx = t & 31;
    const int ty = t >> 5;       // 0..7
    const int qb = ty << 1;      // 2 q-rows per thread

    for (int c = 0; c < 16; c++) {
        const int buf = c & 1;
        __half2 pre[8];
        if (c < 15) {
            const __half2* src = kp + (size_t)(c + 1) * 64 * 32;
#pragma unroll
            for (int j = 0; j < 8; j++) pre[j] = src[t + j * 256];
        }

        float facc[2][2] = {};
#pragma unroll
        for (int grp = 0; grp < 8; grp++) {
            __half2 acc2[2][2];
#pragma unroll
            for (int i = 0; i < 2; i++) {
                acc2[i][0] = __floats2half2_rn(0.f, 0.f);
                acc2[i][1] = __floats2half2_rn(0.f, 0.f);
            }
#pragma unroll
            for (int u = 0; u < 4; u++) {
                const int hp = grp * 4 + u;
                const __half2 w2  = s_wv[hp];
                const __half2 k20 = s_kp[buf][tx][hp];
                const __half2 k21 = s_kp[buf][tx + 32][hp];
#pragma unroll
                for (int i = 0; i < 2; i++) {
                    const __half2 q2 = s_qp[qb + i][hp];
                    __half2 xa = __hadd2(q2, k20);
                    __half2 xb = __hadd2(q2, k21);
                    uint32_t ta = tanh2(*(uint32_t*)&xa);
                    uint32_t tb = tanh2(*(uint32_t*)&xb);
                    acc2[i][0] = __hfma2(w2, *(__half2*)&ta, acc2[i][0]);
                    acc2[i][1] = __hfma2(w2, *(__half2*)&tb, acc2[i][1]);
                }
            }
#pragma unroll
            for (int i = 0; i < 2; i++) {
#pragma unroll
                for (int j = 0; j < 2; j++) {
                    float2 f = __half22float2(acc2[i][j]);
                    facc[i][j] += f.x + f.y;
                }
            }
        }

        const int kc = c * 64;
#pragma unroll
        for (int i = 0; i < 2; i++) {
            s_sc[qb + i][kc + tx]      = facc[i][0];
            s_sc[qb + i][kc + tx + 32] = facc[i][1];
        }

        if (c < 15) {
#pragma unroll
            for (int j = 0; j < 8; j++) {
                int i = t + j * 256;
                s_kp[buf ^ 1][i >> 5][i & 31] = pre[j];
            }
        }
        __syncthreads();
    }

    // ---- softmax: 8 warps x 2 rows, emit fp16 attn ----
    const int lane = t & 31;
    const int warp = t >> 5;
#pragma unroll
    for (int rr = 0; rr < 2; rr++) {
        const int r = warp * 2 + rr;
        float* row = s_sc[r];

        float m = -1e30f;
#pragma unroll
        for (int i = 0; i < 32; i++) m = fmaxf(m, row[lane + 32 * i]);
#pragma unroll
        for (int o = 16; o; o >>= 1) m = fmaxf(m, __shfl_xor_sync(~0u, m, o));

        float ssum = 0.f;
#pragma unroll
        for (int i = 0; i < 32; i++) {
            float e = __expf(row[lane + 32 * i] - m);
            row[lane + 32 * i] = e;
            ssum += e;
        }
#pragma unroll
        for (int o = 16; o; o >>= 1) ssum += __shfl_xor_sync(~0u, ssum, o);
        const float inv = 1.0f / ssum;

        const size_t rowbase = ((size_t)(b * 1024 + q0 + r)) * 1024;
#pragma unroll
        for (int i = 0; i < 32; i++) {
            float a = row[lane + 32 * i] * inv;
            g_a[rowbase + lane + 32 * i] = __float2half_rn(a);
        }
    }
}

// ---------------------------------------------------------------------------
// AV GEMM: CTA tile 32(M) x 128(N), grid 256, 8 warps (16x32 each),
// 3-stage cp.async, 1 sync/iter. (R14, unchanged)
// ---------------------------------------------------------------------------
#define AS_ROW 40
#define BS_ROW 136
#define NSTG 3
#define STG_A_BYTES (32 * AS_ROW * 2)      // 2560
#define STG_B_BYTES (32 * BS_ROW * 2)      // 8704
#define SMEM_A_BYTES (NSTG * STG_A_BYTES)  // 7680
#define SMEM_B_BYTES (NSTG * STG_B_BYTES)  // 26112
#define SMEM_TOTAL_AV (SMEM_A_BYTES + SMEM_B_BYTES)   // 33792

__global__ __launch_bounds__(256)
void av_mma_kernel(float* __restrict__ Out)
{
    extern __shared__ char dyn[];
    const uint32_t sA = s2u(dyn);
    const uint32_t sB = s2u(dyn + SMEM_A_BYTES);

    const int t = threadIdx.x, wid = t >> 5, lane = t & 31;
    const int wm = wid & 1;
    const int wn = wid >> 1;
    const int b = blockIdx.z;
    const int m0 = blockIdx.y * 32;
    const int n0 = blockIdx.x * 128;

    const __half* Ag = g_a + ((size_t)b * 1024 + m0) * 1024;
    const __half* Vg = g_v + (size_t)b * 1024 * 256 + n0;

    const int a_row = t >> 2, a_col = (t & 3) * 8;
    const int b_row = t >> 4, b_col = (t & 15) * 8;

    const int sub = lane >> 3, r8 = lane & 7;
    const uint32_t a_lane_off = (uint32_t)(((sub & 1) * 8 + r8) * (AS_ROW * 2) + (sub >> 1) * 16);
    const uint32_t b_lane_off = (uint32_t)(((sub & 1) * 8 + r8) * (BS_ROW * 2) + (sub >> 1) * 16);

    auto issue = [&](int step, int buf) {
        const size_t kb = (size_t)step * 32;
        if (t < 128)
            cp16(sA + (uint32_t)(buf * STG_A_BYTES) + (uint32_t)((a_row * AS_ROW + a_col) * 2),
                 Ag + (size_t)a_row * 1024 + kb + a_col);
#pragma unroll
        for (int rr = 0; rr < 2; rr++) {
            const int row = b_row + rr * 16;
            cp16(sB + (uint32_t)(buf * STG_B_BYTES) + (uint32_t)((row * BS_ROW + b_col) * 2),
                 Vg + (kb + row) * 256 + b_col);
        }
    };

    float acc[4][4] = {};

    issue(0, 0); cp_commit();
    issue(1, 1); cp_commit();

    int buf = 0;
    for (int s = 0; s < 32; s++) {
        if (s < 31) cp_wait<1>(); else cp_wait<0>();
        __syncthreads();
        if (s < 30) {
            int nb = buf + 2; if (nb >= NSTG) nb -= NSTG;
            issue(s + 2, nb);
            cp_commit();
        }

#pragma unroll
        for (int k0 = 0; k0 < 32; k0 += 16) {
            uint32_t Af[4];
            {
                uint32_t addr = sA + (uint32_t)(buf * STG_A_BYTES)
                              + (uint32_t)((wm * 16 * AS_ROW + k0) * 2) + a_lane_off;
                ldsm4(Af, addr);
            }
            uint32_t Bf[4][2];
#pragma unroll
            for (int ntp = 0; ntp < 2; ntp++) {
                uint32_t rr[4];
                uint32_t addr = sB + (uint32_t)(buf * STG_B_BYTES)
                              + (uint32_t)((k0 * BS_ROW) * 2)
                              + (uint32_t)(wn * 64 + ntp * 32) + b_lane_off;
                ldsm4t(rr, addr);
                Bf[ntp * 2][0] = rr[0]; Bf[ntp * 2][1] = rr[1];
                Bf[ntp * 2 + 1][0] = rr[2]; Bf[ntp * 2 + 1][1] = rr[3];
            }
#pragma unroll
            for (int nt = 0; nt < 4; nt++)
                mma_f16(acc[nt], Af, Bf[nt]);
        }
        buf++; if (buf >= NSTG) buf -= NSTG;
    }

    const int g  = lane >> 2;
    const int tq = lane & 3;
    float* Ob = Out + (size_t)b * 1024 * 256;
#pragma unroll
    for (int nt = 0; nt < 4; nt++) {
        int row = m0 + wm * 16 + g;
        int col = n0 + wn * 32 + nt * 8 + tq * 2;
        *(float2*)(Ob + (size_t)row * 256 + col)       = make_float2(acc[nt][0], acc[nt][1]);
        *(float2*)(Ob + (size_t)(row + 8) * 256 + col) = make_float2(acc[nt][2], acc[nt][3]);
    }
}

// ---------------------------------------------------------------------------
extern "C" void kernel_launch(void* const* d_in, const int* in_sizes, int n_in,
                              void* d_out, int out_size)
{
    (void)in_sizes; (void)n_in; (void)out_size;
    const float* queries = (const float*)d_in[0];
    const float* keys    = (const float*)d_in[1];
    const float* values  = (const float*)d_in[2];
    const float* W_q     = (const float*)d_in[3];
    const float* W_k     = (const float*)d_in[4];
    const float* w_v     = (const float*)d_in[5];
    float* out = (float*)d_out;

    cudaFuncSetAttribute(proj_vsplit_kernel, cudaFuncAttributeMaxDynamicSharedMemorySize, PJ_SMEM_TOTAL);
    cudaFuncSetAttribute(av_mma_kernel, cudaFuncAttributeMaxDynamicSharedMemorySize, SMEM_TOTAL_AV);
    cudaFuncSetAttribute(scores_softmax_kernel, cudaFuncAttributeMaxDynamicSharedMemorySize, SMEM_SC_TOTAL);

    // 1. projections via bf16x3 HMMA (256 threads) + values fp16 convert
    proj_vsplit_kernel<<<dim3(1, 256, 1), 256, PJ_SMEM_TOTAL>>>(queries, keys, W_q, W_k, values);

    // 2. fused additive-tanh scores + softmax (QT=16, 2 CTAs/SM, grid 256)
    scores_softmax_kernel<<<dim3(Qv / QT, Bv), 256, SMEM_SC_TOTAL>>>(w_v);

    // 3. out = attn @ values via fp16 HMMA (32x128 tiles, grid 256)
    av_mma_kernel<<<dim3(DVv / 128, Qv / 32, Bv), 256, SMEM_TOTAL_AV>>>(out);
}

// round 16
// speedup vs baseline: 1.0350x; 1.0350x over previous
#include <cuda_runtime.h>
#include <cuda_bf16.h>
#include <cuda_fp16.h>
#include <cstdint>
#include <cstddef>

// Problem dims
#define Bv  4
#define Qv  1024
#define Kv  1024
#define Dv  256
#define Hv  64
#define DVv 256

// Scratch (allocation-free rule: __device__ globals)
__device__ __align__(16) __half g_qp[Bv * Qv * Hv];                 // 512 KB
__device__ __align__(16) __half g_kp[Bv * Kv * Hv];                 // 512 KB
__device__ __align__(16) __half g_a[(size_t)Bv * Qv * Kv];          // 8 MB  (fp16 attn)
__device__ __align__(16) __half g_v[Bv * Kv * DVv];                 // 2 MB  (fp16 values)

__device__ __forceinline__ uint32_t tanh2(uint32_t x) {
    uint32_t y;
    asm("tanh.approx.f16x2 %0, %1;" : "=r"(y) : "r"(x));
    return y;
}

__device__ __forceinline__ uint32_t s2u(const void* p) {
    uint32_t a;
    asm("{ .reg .u64 t; cvta.to.shared.u64 t, %1; cvt.u32.u64 %0, t; }" : "=r"(a) : "l"(p));
    return a;
}

__device__ __forceinline__ void cp16(uint32_t dst, const void* src) {
    asm volatile("cp.async.cg.shared.global [%0], [%1], 16;" :: "r"(dst), "l"(src));
}
__device__ __forceinline__ void cp_commit() { asm volatile("cp.async.commit_group;"); }
template <int N> __device__ __forceinline__ void cp_wait() {
    asm volatile("cp.async.wait_group %0;" :: "n"(N));
}

__device__ __forceinline__ void ldsm4(uint32_t* r, uint32_t addr) {
    asm volatile("ldmatrix.sync.aligned.m8n8.x4.shared.b16 {%0,%1,%2,%3}, [%4];"
                 : "=r"(r[0]), "=r"(r[1]), "=r"(r[2]), "=r"(r[3]) : "r"(addr));
}
__device__ __forceinline__ void ldsm4t(uint32_t* r, uint32_t addr) {
    asm volatile("ldmatrix.sync.aligned.m8n8.x4.trans.shared.b16 {%0,%1,%2,%3}, [%4];"
                 : "=r"(r[0]), "=r"(r[1]), "=r"(r[2]), "=r"(r[3]) : "r"(addr));
}
__device__ __forceinline__ void mma_bf16(float* d, const uint32_t* a, const uint32_t* b) {
    asm volatile(
        "mma.sync.aligned.m16n8k16.row.col.f32.bf16.bf16.f32 "
        "{%0,%1,%2,%3},{%4,%5,%6,%7},{%8,%9},{%0,%1,%2,%3};"
        : "+f"(d[0]), "+f"(d[1]), "+f"(d[2]), "+f"(d[3])
        : "r"(a[0]), "r"(a[1]), "r"(a[2]), "r"(a[3]), "r"(b[0]), "r"(b[1]));
}
__device__ __forceinline__ void mma_f16(float* d, const uint32_t* a, const uint32_t* b) {
    asm volatile(
        "mma.sync.aligned.m16n8k16.row.col.f32.f16.f16.f32 "
        "{%0,%1,%2,%3},{%4,%5,%6,%7},{%8,%9},{%0,%1,%2,%3};"
        : "+f"(d[0]), "+f"(d[1]), "+f"(d[2]), "+f"(d[3])
        : "r"(a[0]), "r"(a[1]), "r"(a[2]), "r"(a[3]), "r"(b[0]), "r"(b[1]));
}

__device__ __forceinline__ void bfsplit2(float x, float y, uint32_t& hi, uint32_t& lo) {
    __nv_bfloat16 hx = __float2bfloat16(x), hy = __float2bfloat16(y);
    __nv_bfloat16 lx = __float2bfloat16(x - __bfloat162float(hx));
    __nv_bfloat16 ly = __float2bfloat16(y - __bfloat162float(hy));
    hi = (uint32_t)*(uint16_t*)&hx | ((uint32_t)*(uint16_t*)&hy << 16);
    lo = (uint32_t)*(uint16_t*)&lx | ((uint32_t)*(uint16_t*)&ly << 16);
}

// ---------------------------------------------------------------------------
// Fused: projections via bf16x3 HMMA + values fp16 convert. (R15 proj, 14.5us)
// grid (1, 256), 256 threads: y<64 Q tiles (64 rows), y<128 K tiles, else vconv.
// 8 warps, warp tile 16(M) x 32(N).
// ---------------------------------------------------------------------------
#define PW_STRIDE 72
#define PA_STRIDE 40
#define PJ_WPLANE (256 * PW_STRIDE * 2)     // 36864 B
#define PJ_W_BYTES (2 * PJ_WPLANE)          // 73728
#define PJ_APLANE (64 * PA_STRIDE * 2)      // 5120 B
#define PJ_ABUF   (2 * PJ_APLANE)           // 10240 per stage
#define PJ_SMEM_TOTAL (PJ_W_BYTES + 2 * PJ_ABUF)   // 94208

__global__ __launch_bounds__(256)
void proj_vsplit_kernel(const float* __restrict__ Qg, const float* __restrict__ Kg,
                        const float* __restrict__ Wq, const float* __restrict__ Wk,
                        const float* __restrict__ Vg)
{
    if (blockIdx.y >= 128) {
        const int blk = blockIdx.y - 128;          // 0..127
#pragma unroll
        for (int it = 0; it < 8; it++) {
            size_t idx4 = (size_t)blk * 256 + threadIdx.x + (size_t)it * 32768;
            size_t i = idx4 * 4;
            float4 v = *(const float4*)(Vg + i);
            __half2 p01 = __floats2half2_rn(v.x, v.y);
            __half2 p23 = __floats2half2_rn(v.z, v.w);
            *(uint2*)(g_v + i) = make_uint2(*(uint32_t*)&p01, *(uint32_t*)&p23);
        }
        return;
    }

    extern __shared__ char psm[];
    char* wh = psm;
    char* wl = psm + PJ_WPLANE;
    char* ab = psm + PJ_W_BYTES;
    const uint32_t sWH = s2u(wh);
    const uint32_t sWL = s2u(wl);
    const uint32_t sAB = s2u(ab);

    const bool isQ = blockIdx.y < 64;
    const int tile = blockIdx.y & 63;
    const float* A = (isQ ? Qg : Kg) + (size_t)tile * 64 * 256;
    const float* W = isQ ? Wq : Wk;
    __half*      C = (isQ ? g_qp : g_kp) + (size_t)tile * 64 * 64;

    const int t = threadIdx.x;
    const int wid = t >> 5, lane = t & 31;
    const int wm = wid & 3;
    const int wn = wid >> 2;

    const int ar = t >> 2;                 // 0..63
    const int akc = (t & 3) * 8;           // 0,8,16,24
    float4 rA[2], rB[2];

    auto ldgA = [&](int s, float4* rg) {
        const float* src = A + (size_t)ar * 256 + s * 32 + akc;
        rg[0] = *(const float4*)(src);
        rg[1] = *(const float4*)(src + 4);
    };
    auto stsA = [&](const float4* rg, int buf) {
        char* hb = ab + buf * PJ_ABUF + (ar * PA_STRIDE + akc) * 2;
        char* lb = hb + PJ_APLANE;
#pragma unroll
        for (int j = 0; j < 2; j++) {
            uint32_t h01, l01, h23, l23;
            bfsplit2(rg[j].x, rg[j].y, h01, l01);
            bfsplit2(rg[j].z, rg[j].w, h23, l23);
            *(uint2*)(hb + j * 8) = make_uint2(h01, h23);
            *(uint2*)(lb + j * 8) = make_uint2(l01, l23);
        }
    };

    ldgA(0, rA);

#pragma unroll
    for (int i = 0; i < 16; i++) {
        int idx = t + i * 256;
        int row = idx >> 4;
        int c4 = (idx & 15) * 4;
        float4 v = *(const float4*)(W + (size_t)row * 64 + c4);
        uint32_t h01, l01, h23, l23;
        bfsplit2(v.x, v.y, h01, l01);
        bfsplit2(v.z, v.w, h23, l23);
        *(uint2*)(wh + (row * PW_STRIDE + c4) * 2) = make_uint2(h01, h23);
        *(uint2*)(wl + (row * PW_STRIDE + c4) * 2) = make_uint2(l01, l23);
    }

    stsA(rA, 0);
    __syncthreads();

    const int sub = lane >> 3, r8 = lane & 7;
    const uint32_t a_off = (uint32_t)(((sub & 1) * 8 + r8) * (PA_STRIDE * 2) + (sub >> 1) * 16);
    const uint32_t w_off = (uint32_t)(((sub & 1) * 8 + r8) * (PW_STRIDE * 2) + (sub >> 1) * 16);

    float acc[4][4] = {};

    for (int s = 0; s < 8; s++) {
        const int buf = s & 1;
        if (s < 7) ldgA(s + 1, rB);

#pragma unroll
        for (int kk2 = 0; kk2 < 2; kk2++) {
            const int kk = kk2 * 16;
            const int kg = s * 32 + kk;
            uint32_t Ah4[4], Al4[4];
            {
                uint32_t base = sAB + (uint32_t)(buf * PJ_ABUF)
                              + (uint32_t)((wm * 16 * PA_STRIDE + kk) * 2) + a_off;
                ldsm4(Ah4, base);
                ldsm4(Al4, base + PJ_APLANE);
            }
            uint32_t Wh4[4][2], Wl4[4][2];
#pragma unroll
            for (int p = 0; p < 2; p++) {
                uint32_t rr[4];
                uint32_t co = (uint32_t)(kg * PW_STRIDE * 2) + (uint32_t)(wn * 64 + p * 32) + w_off;
                ldsm4t(rr, sWH + co);
                Wh4[2 * p][0] = rr[0]; Wh4[2 * p][1] = rr[1];
                Wh4[2 * p + 1][0] = rr[2]; Wh4[2 * p + 1][1] = rr[3];
                ldsm4t(rr, sWL + co);
                Wl4[2 * p][0] = rr[0]; Wl4[2 * p][1] = rr[1];
                Wl4[2 * p + 1][0] = rr[2]; Wl4[2 * p + 1][1] = rr[3];
            }
#pragma unroll
            for (int nt = 0; nt < 4; nt++) {
                mma_bf16(acc[nt], Ah4, Wh4[nt]);
                mma_bf16(acc[nt], Ah4, Wl4[nt]);
                mma_bf16(acc[nt], Al4, Wh4[nt]);
            }
        }

        if (s < 7) stsA(rB, buf ^ 1);
        __syncthreads();
    }

    const int g = lane >> 2, tq = lane & 3;
#pragma unroll
    for (int nt = 0; nt < 4; nt++) {
        int col = wn * 32 + nt * 8 + tq * 2;
        int row0 = wm * 16 + g;
        __half2 p0 = __floats2half2_rn(acc[nt][0], acc[nt][1]);
        __half2 p1 = __floats2half2_rn(acc[nt][2], acc[nt][3]);
        *(__half2*)(C + (size_t)row0 * 64 + col)       = p0;
        *(__half2*)(C + (size_t)(row0 + 8) * 64 + col) = p1;
    }
}

// ---------------------------------------------------------------------------
// Fused scores + softmax (QT=32), 512 threads. (R14, part of 98.78 config)
// One CTA: 32 q-rows x all K=1024. Each thread: 2 q-rows x 2 k-slots.
// ---------------------------------------------------------------------------
#define QT 32
#define SC_BYTES   (QT * 1024 * 4)
#define QP_OFF     SC_BYTES
#define QP_BYTES   (QT * 33 * 8)
#define KP_OFF     (QP_OFF + QP_BYTES)
#define KP_BYTES   (2 * 64 * 33 * 4)
#define WV_OFF     (KP_OFF + KP_BYTES)
#define SMEM_SC_TOTAL (WV_OFF + 128)

__global__ __launch_bounds__(512)
void scores_softmax_kernel(const float* __restrict__ wv_g)
{
    extern __shared__ char sm[];
    float   (*s_sc)[1024]   = (float(*)[1024])sm;
    __half2 (*s_qp)[33]     = (__half2(*)[33])(sm + QP_OFF);
    __half2 (*s_kp)[64][33] = (__half2(*)[64][33])(sm + KP_OFF);
    __half2* s_wv           = (__half2*)(sm + WV_OFF);

    const int t  = threadIdx.x;
    const int b  = blockIdx.y;
    const int q0 = blockIdx.x * QT;

    const __half2* qp = (const __half2*)(g_qp + ((size_t)b * Qv + q0) * Hv);
    const __half2* kp = (const __half2*)(g_kp + (size_t)b * Kv * Hv);

#pragma unroll
    for (int j = 0; j < 2; j++) {
        int i = t + j * 512;
        s_qp[i >> 5][i & 31] = qp[i];
    }
    if (t < 32) s_wv[t] = __floats2half2_rn(wv_g[2 * t], wv_g[2 * t + 1]);

#pragma unroll
    for (int j = 0; j < 4; j++) {
        int i = t + j * 512;
        s_kp[0][i >> 5][i & 31] = kp[i];
    }
    __syncthreads();

    const int tx = t & 31;
    const int ty = t >> 5;       // 0..15
    const int qb = ty << 1;      // 2 q-rows per thread

    for (int c = 0; c < 16; c++) {
        const int buf = c & 1;
        __half2 pre[4];
        if (c < 15) {
            const __half2* src = kp + (size_t)(c + 1) * 64 * 32;
#pragma unroll
            for (int j = 0; j < 4; j++) pre[j] = src[t + j * 512];
        }

        float facc[2][2] = {};
#pragma unroll
        for (int grp = 0; grp < 8; grp++) {
            __half2 acc2[2][2];
#pragma unroll
            for (int i = 0; i < 2; i++) {
                acc2[i][0] = __floats2half2_rn(0.f, 0.f);
                acc2[i][1] = __floats2half2_rn(0.f, 0.f);
            }
#pragma unroll
            for (int u = 0; u < 4; u++) {
                const int hp = grp * 4 + u;
                const __half2 w2  = s_wv[hp];
                const __half2 k20 = s_kp[buf][tx][hp];
                const __half2 k21 = s_kp[buf][tx + 32][hp];
#pragma unroll
                for (int i = 0; i < 2; i++) {
                    const __half2 q2 = s_qp[qb + i][hp];
                    __half2 xa = __hadd2(q2, k20);
                    __half2 xb = __hadd2(q2, k21);
                    uint32_t ta = tanh2(*(uint32_t*)&xa);
                    uint32_t tb = tanh2(*(uint32_t*)&xb);
                    acc2[i][0] = __hfma2(w2, *(__half2*)&ta, acc2[i][0]);
                    acc2[i][1] = __hfma2(w2, *(__half2*)&tb, acc2[i][1]);
                }
            }
#pragma unroll
            for (int i = 0; i < 2; i++) {
#pragma unroll
                for (int j = 0; j < 2; j++) {
                    float2 f = __half22float2(acc2[i][j]);
                    facc[i][j] += f.x + f.y;
                }
            }
        }

        const int kc = c * 64;
#pragma unroll
        for (int i = 0; i < 2; i++) {
            s_sc[qb + i][kc + tx]      = facc[i][0];
            s_sc[qb + i][kc + tx + 32] = facc[i][1];
        }

        if (c < 15) {
#pragma unroll
            for (int j = 0; j < 4; j++) {
                int i = t + j * 512;
                s_kp[buf ^ 1][i >> 5][i & 31] = pre[j];
            }
        }
        __syncthreads();
    }

    // ---- softmax: 16 warps x 2 rows, emit fp16 attn ----
    const int lane = t & 31;
    const int warp = t >> 5;
#pragma unroll
    for (int rr = 0; rr < 2; rr++) {
        const int r = warp * 2 + rr;
        float* row = s_sc[r];

        float m = -1e30f;
#pragma unroll
        for (int i = 0; i < 32; i++) m = fmaxf(m, row[lane + 32 * i]);
#pragma unroll
        for (int o = 16; o; o >>= 1) m = fmaxf(m, __shfl_xor_sync(~0u, m, o));

        float ssum = 0.f;
#pragma unroll
        for (int i = 0; i < 32; i++) {
            float e = __expf(row[lane + 32 * i] - m);
            row[lane + 32 * i] = e;
            ssum += e;
        }
#pragma unroll
        for (int o = 16; o; o >>= 1) ssum += __shfl_xor_sync(~0u, ssum, o);
        const float inv = 1.0f / ssum;

        const size_t rowbase = ((size_t)(b * 1024 + q0 + r)) * 1024;
#pragma unroll
        for (int i = 0; i < 32; i++) {
            float a = row[lane + 32 * i] * inv;
            g_a[rowbase + lane + 32 * i] = __float2half_rn(a);
        }
    }
}

// ---------------------------------------------------------------------------
// AV GEMM: CTA tile 32(M) x 128(N), grid 256, 8 warps (16x32 each),
// 3-stage cp.async, 1 sync/iter. (R14, part of 98.78 config)
// ---------------------------------------------------------------------------
#define AS_ROW 40
#define BS_ROW 136
#define NSTG 3
#define STG_A_BYTES (32 * AS_ROW * 2)      // 2560
#define STG_B_BYTES (32 * BS_ROW * 2)      // 8704
#define SMEM_A_BYTES (NSTG * STG_A_BYTES)  // 7680
#define SMEM_B_BYTES (NSTG * STG_B_BYTES)  // 26112
#define SMEM_TOTAL_AV (SMEM_A_BYTES + SMEM_B_BYTES)   // 33792

__global__ __launch_bounds__(256)
void av_mma_kernel(float* __restrict__ Out)
{
    extern __shared__ char dyn[];
    const uint32_t sA = s2u(dyn);
    const uint32_t sB = s2u(dyn + SMEM_A_BYTES);

    const int t = threadIdx.x, wid = t >> 5, lane = t & 31;
    const int wm = wid & 1;
    const int wn = wid >> 1;
    const int b = blockIdx.z;
    const int m0 = blockIdx.y * 32;
    const int n0 = blockIdx.x * 128;

    const __half* Ag = g_a + ((size_t)b * 1024 + m0) * 1024;
    const __half* Vg = g_v + (size_t)b * 1024 * 256 + n0;

    const int a_row = t >> 2, a_col = (t & 3) * 8;
    const int b_row = t >> 4, b_col = (t & 15) * 8;

    const int sub = lane >> 3, r8 = lane & 7;
    const uint32_t a_lane_off = (uint32_t)(((sub & 1) * 8 + r8) * (AS_ROW * 2) + (sub >> 1) * 16);
    const uint32_t b_lane_off = (uint32_t)(((sub & 1) * 8 + r8) * (BS_ROW * 2) + (sub >> 1) * 16);

    auto issue = [&](int step, int buf) {
        const size_t kb = (size_t)step * 32;
        if (t < 128)
            cp16(sA + (uint32_t)(buf * STG_A_BYTES) + (uint32_t)((a_row * AS_ROW + a_col) * 2),
                 Ag + (size_t)a_row * 1024 + kb + a_col);
#pragma unroll
        for (int rr = 0; rr < 2; rr++) {
            const int row = b_row + rr * 16;
            cp16(sB + (uint32_t)(buf * STG_B_BYTES) + (uint32_t)((row * BS_ROW + b_col) * 2),
                 Vg + (kb + row) * 256 + b_col);
        }
    };

    float acc[4][4] = {};

    issue(0, 0); cp_commit();
    issue(1, 1); cp_commit();

    int buf = 0;
    for (int s = 0; s < 32; s++) {
        if (s < 31) cp_wait<1>(); else cp_wait<0>();
        __syncthreads();
        if (s < 30) {
            int nb = buf + 2; if (nb >= NSTG) nb -= NSTG;
            issue(s + 2, nb);
            cp_commit();
        }

#pragma unroll
        for (int k0 = 0; k0 < 32; k0 += 16) {
            uint32_t Af[4];
            {
                uint32_t addr = sA + (uint32_t)(buf * STG_A_BYTES)
                              + (uint32_t)((wm * 16 * AS_ROW + k0) * 2) + a_lane_off;
                ldsm4(Af, addr);
            }
            uint32_t Bf[4][2];
#pragma unroll
            for (int ntp = 0; ntp < 2; ntp++) {
                uint32_t rr[4];
                uint32_t addr = sB + (uint32_t)(buf * STG_B_BYTES)
                              + (uint32_t)((k0 * BS_ROW) * 2)
                              + (uint32_t)(wn * 64 + ntp * 32) + b_lane_off;
                ldsm4t(rr, addr);
                Bf[ntp * 2][0] = rr[0]; Bf[ntp * 2][1] = rr[1];
                Bf[ntp * 2 + 1][0] = rr[2]; Bf[ntp * 2 + 1][1] = rr[3];
            }
#pragma unroll
            for (int nt = 0; nt < 4; nt++)
                mma_f16(acc[nt], Af, Bf[nt]);
        }
        buf++; if (buf >= NSTG) buf -= NSTG;
    }

    const int g  = lane >> 2;
    const int tq = lane & 3;
    float* Ob = Out + (size_t)b * 1024 * 256;
#pragma unroll
    for (int nt = 0; nt < 4; nt++) {
        int row = m0 + wm * 16 + g;
        int col = n0 + wn * 32 + nt * 8 + tq * 2;
        *(float2*)(Ob + (size_t)row * 256 + col)       = make_float2(acc[nt][0], acc[nt][1]);
        *(float2*)(Ob + (size_t)(row + 8) * 256 + col) = make_float2(acc[nt][2], acc[nt][3]);
    }
}

// ---------------------------------------------------------------------------
extern "C" void kernel_launch(void* const* d_in, const int* in_sizes, int n_in,
                              void* d_out, int out_size)
{
    (void)in_sizes; (void)n_in; (void)out_size;
    const float* queries = (const float*)d_in[0];
    const float* keys    = (const float*)d_in[1];
    const float* values  = (const float*)d_in[2];
    const float* W_q     = (const float*)d_in[3];
    const float* W_k     = (const float*)d_in[4];
    const float* w_v     = (const float*)d_in[5];
    float* out = (float*)d_out;

    cudaFuncSetAttribute(proj_vsplit_kernel, cudaFuncAttributeMaxDynamicSharedMemorySize, PJ_SMEM_TOTAL);
    cudaFuncSetAttribute(av_mma_kernel, cudaFuncAttributeMaxDynamicSharedMemorySize, SMEM_TOTAL_AV);
    cudaFuncSetAttribute(scores_softmax_kernel, cudaFuncAttributeMaxDynamicSharedMemorySize, SMEM_SC_TOTAL);

    // 1. projections via bf16x3 HMMA (256 threads) + values fp16 convert
    proj_vsplit_kernel<<<dim3(1, 256, 1), 256, PJ_SMEM_TOTAL>>>(queries, keys, W_q, W_k, values);

    // 2. fused additive-tanh scores + softmax (QT=32, 512 threads)
    scores_softmax_kernel<<<dim3(Qv / QT, Bv), 512, SMEM_SC_TOTAL>>>(w_v);

    // 3. out = attn @ values via fp16 HMMA (32x128 tiles, grid 256)
    av_mma_kernel<<<dim3(DVv / 128, Qv / 32, Bv), 256, SMEM_TOTAL_AV>>>(out);
}